// round 1
// baseline (speedup 1.0000x reference)
#include <cuda_runtime.h>
#include <math.h>
#include <float.h>

#define B_   128
#define T_   1000
#define DV_  256
#define ROWS_ (B_*T_)

// scratch (no allocs allowed)
__device__ float g_qpart[B_*DV_];
__device__ float g_rel[ROWS_];

__device__ __forceinline__ float gelu_f(float v) {
    return 0.5f * v * (1.0f + erff(v * 0.7071067811865475f));
}
__device__ __forceinline__ float warpSum(float v) {
#pragma unroll
    for (int o = 16; o > 0; o >>= 1) v += __shfl_down_sync(0xffffffffu, v, o);
    return v;
}

// ---------------------------------------------------------------------------
// Kernel 1: per-batch MLPs -> mu_q, sigma, qpart.  128 blocks x 256 threads.
// ---------------------------------------------------------------------------
__global__ __launch_bounds__(256) void k_params(
    const float* __restrict__ qe,
    const float* __restrict__ mu_w1, const float* __restrict__ mu_b1,
    const float* __restrict__ mu_w2, const float* __restrict__ mu_b2,
    const float* __restrict__ ln_g,  const float* __restrict__ ln_b,
    const float* __restrict__ sg_w1, const float* __restrict__ sg_b1,
    const float* __restrict__ sg_w2, const float* __restrict__ sg_b2,
    const float* __restrict__ sel_w1,const float* __restrict__ sel_b1,
    float* __restrict__ out_mu, float* __restrict__ out_sig)
{
    __shared__ float q[256];
    __shared__ float h[512];
    __shared__ float red[8];
    int b = blockIdx.x, tid = threadIdx.x;
    int lane = tid & 31, wid = tid >> 5;

    q[tid] = qe[b*256 + tid];
    __syncthreads();

    // mu hidden (512)
    for (int jj = 0; jj < 2; jj++) {
        int j = tid + jj*256;
        float acc = mu_b1[j];
        for (int d = 0; d < 256; d++) acc = fmaf(q[d], mu_w1[d*512 + j], acc);
        h[j] = gelu_f(acc);
    }
    __syncthreads();

    float u = mu_b2[tid];
    for (int d = 0; d < 512; d++) u = fmaf(h[d], mu_w2[d*256 + tid], u);

    // layernorm over 256
    float s = warpSum(u);
    if (lane == 0) red[wid] = s;
    __syncthreads();
    if (tid == 0) { float t = 0; for (int w = 0; w < 8; w++) t += red[w]; red[0] = t; }
    __syncthreads();
    float mean = red[0] * (1.0f/256.0f);
    __syncthreads();
    float df = u - mean;
    float s2 = warpSum(df*df);
    if (lane == 0) red[wid] = s2;
    __syncthreads();
    if (tid == 0) { float t = 0; for (int w = 0; w < 8; w++) t += red[w]; red[0] = t; }
    __syncthreads();
    float var = red[0] * (1.0f/256.0f);
    out_mu[b*256 + tid] = df * rsqrtf(var + 1e-5f) * ln_g[tid] + ln_b[tid];
    __syncthreads();

    // sigma (reuse h[0..255])
    {
        float acc = sg_b1[tid];
        for (int d = 0; d < 256; d++) acc = fmaf(q[d], sg_w1[d*256 + tid], acc);
        h[tid] = gelu_f(acc);
    }
    __syncthreads();
    {
        float acc = sg_b2[tid];
        for (int d = 0; d < 256; d++) acc = fmaf(h[d], sg_w2[d*256 + tid], acc);
        out_sig[b*256 + tid] = 1.0f/(1.0f + expf(-acc)) * 2.0f + 0.1f;
    }
    // qpart = q @ sel_w1[256:512,:] + sel_b1
    {
        float acc = sel_b1[tid];
        for (int d = 0; d < 256; d++) acc = fmaf(q[d], sel_w1[(256 + d)*256 + tid], acc);
        g_qpart[b*256 + tid] = acc;
    }
}

// ---------------------------------------------------------------------------
// Kernel 2: x = vf + pos (write out), dist per row.  128000 blocks x 256 thr.
// ---------------------------------------------------------------------------
__global__ __launch_bounds__(256) void k_xdist(
    const float* __restrict__ vf, const float* __restrict__ pos,
    const float* __restrict__ mu, const float* __restrict__ sig,
    float* __restrict__ x_out, float* __restrict__ dist_out)
{
    __shared__ float red[8];
    int row = blockIdx.x;
    int b = row / T_;
    int t = row - b*T_;
    int d = threadIdx.x;

    float xv = vf[(size_t)row*256 + d] + pos[t*256 + d];
    x_out[(size_t)row*256 + d] = xv;
    float c = xv - mu[b*256 + d];
    float v = c*c / (sig[b*256 + d] + 1e-8f);
    int lane = d & 31, wid = d >> 5;
    v = warpSum(v);
    if (lane == 0) red[wid] = v;
    __syncthreads();
    if (d == 0) {
        float tot = 0;
        for (int w = 0; w < 8; w++) tot += red[w];
        dist_out[row] = fmaxf(tot, 1e-8f);
    }
}

// ---------------------------------------------------------------------------
// Kernel 3: rel = gelu(x @ W1[:256] + qpart) @ w2 + b2.
// Tiled fp32 GEMM: block = 64 rows x 256 cols, thread tile 8x8, K-chunks of 16.
// ---------------------------------------------------------------------------
#define BR 64
#define KC 16
__global__ __launch_bounds__(256) void k_rel(
    const float* __restrict__ x, const float* __restrict__ W1,
    const float* __restrict__ w2, const float* __restrict__ b2p)
{
    __shared__ float As[KC][BR];
    __shared__ float Bs[KC][256];
    int tid = threadIdx.x;
    int row0 = blockIdx.x * BR;
    int tr = tid >> 5;     // warp id: owns rows tr*8..tr*8+7
    int tc = tid & 31;     // lane: owns cols tc+32*j

    float acc[8][8];
#pragma unroll
    for (int i = 0; i < 8; i++)
#pragma unroll
        for (int j = 0; j < 8; j++) acc[i][j] = 0.f;

    for (int k0 = 0; k0 < 256; k0 += KC) {
        // A tile: 64 x 16
        {
            int r = tid >> 2;
            int kk4 = (tid & 3) * 4;
            float4 av = *reinterpret_cast<const float4*>(
                x + (size_t)(row0 + r)*256 + k0 + kk4);
            As[kk4+0][r] = av.x; As[kk4+1][r] = av.y;
            As[kk4+2][r] = av.z; As[kk4+3][r] = av.w;
        }
        // B tile: 16 x 256
        {
            int kk = tid >> 4;
            int j4 = (tid & 15) * 4;
#pragma unroll
            for (int jb = 0; jb < 4; jb++) {
                float4 bv = *reinterpret_cast<const float4*>(
                    W1 + (size_t)(k0 + kk)*256 + j4 + jb*64);
                *reinterpret_cast<float4*>(&Bs[kk][j4 + jb*64]) = bv;
            }
        }
        __syncthreads();
#pragma unroll
        for (int k = 0; k < KC; k++) {
            float a[8], bb[8];
#pragma unroll
            for (int i = 0; i < 8; i++) a[i] = As[k][tr*8 + i];
#pragma unroll
            for (int j = 0; j < 8; j++) bb[j] = Bs[k][tc + 32*j];
#pragma unroll
            for (int i = 0; i < 8; i++)
#pragma unroll
                for (int j = 0; j < 8; j++)
                    acc[i][j] = fmaf(a[i], bb[j], acc[i][j]);
        }
        __syncthreads();
    }

    float b2 = b2p[0];
#pragma unroll
    for (int i = 0; i < 8; i++) {
        int row = row0 + tr*8 + i;
        int bb_ = row / T_;
        float part = 0.f;
#pragma unroll
        for (int j = 0; j < 8; j++) {
            int col = tc + 32*j;
            float hv = acc[i][j] + g_qpart[bb_*256 + col];
            part = fmaf(gelu_f(hv), w2[col], part);
        }
#pragma unroll
        for (int o = 16; o > 0; o >>= 1) part += __shfl_down_sync(0xffffffffu, part, o);
        if (tc == 0) g_rel[row] = part + b2;
    }
}

// ---------------------------------------------------------------------------
// Kernel 4: per-batch median (rank 499), comb, top-12, diversify, gather.
// 128 blocks x 256 threads.
// ---------------------------------------------------------------------------
__global__ __launch_bounds__(256) void k_select(
    const float* __restrict__ dist, const float* __restrict__ x,
    float* __restrict__ out_rep, float* __restrict__ out_idx)
{
    __shared__ float sdist[T_];
    __shared__ float scomb[1024];
    __shared__ float smed;
    __shared__ float s_wv[8];
    __shared__ int   s_wi[8];
    __shared__ int   s_cand[12];
    __shared__ int   s_sel[6];

    int b = blockIdx.x, tid = threadIdx.x;
    int lane = tid & 31, wid = tid >> 5;

    for (int i = tid; i < T_; i += 256) sdist[i] = dist[b*T_ + i];
    __syncthreads();

    // median: stable rank 499 (lower middle of 1000) == torch/jax sorted[499]
    for (int i = tid; i < T_; i += 256) {
        float e = sdist[i];
        int cnt = 0;
        for (int j = 0; j < T_; j++) {
            float v = sdist[j];
            cnt += (v < e) || (v == e && j < i);
        }
        if (cnt == 499) smed = e;
    }
    __syncthreads();
    float med = smed;

    for (int i = tid; i < 1024; i += 256) {
        if (i < T_) scomb[i] = -fabsf(sdist[i] - med) + 0.5f * g_rel[b*T_ + i];
        else        scomb[i] = -FLT_MAX;
    }
    __syncthreads();

    // iterative top-12, ties -> lowest index (matches lax.top_k membership)
    for (int it = 0; it < 12; it++) {
        float bv = -FLT_MAX; int bi = 1023;
        for (int i = tid; i < 1024; i += 256) {
            float v = scomb[i];
            if (v > bv) { bv = v; bi = i; }
        }
#pragma unroll
        for (int o = 16; o > 0; o >>= 1) {
            float ov = __shfl_down_sync(0xffffffffu, bv, o);
            int   oi = __shfl_down_sync(0xffffffffu, bi, o);
            if (ov > bv || (ov == bv && oi < bi)) { bv = ov; bi = oi; }
        }
        if (lane == 0) { s_wv[wid] = bv; s_wi[wid] = bi; }
        __syncthreads();
        if (tid == 0) {
            float Bv = s_wv[0]; int Bi = s_wi[0];
            for (int w = 1; w < 8; w++)
                if (s_wv[w] > Bv || (s_wv[w] == Bv && s_wi[w] < Bi)) { Bv = s_wv[w]; Bi = s_wi[w]; }
            s_cand[it] = Bi;
            scomb[Bi] = -FLT_MAX;
        }
        __syncthreads();
    }

    if (tid == 0) {
        int c[12];
        for (int i = 0; i < 12; i++) c[i] = s_cand[i];
        // sort candidate indices ascending (jnp.sort(cands))
        for (int i = 1; i < 12; i++) {
            int key = c[i], j = i - 1;
            while (j >= 0 && c[j] > key) { c[j+1] = c[j]; j--; }
            c[j+1] = key;
        }
        int md[12]; bool rem[12];
        for (int i = 0; i < 12; i++) { md[i] = abs(c[i] - c[0]); rem[i] = (i != 0); }
        s_sel[0] = c[0];
        for (int s = 1; s < 6; s++) {
            int best = -2, bi = 0;
            for (int i = 0; i < 12; i++) {
                int sc = rem[i] ? md[i] : -1;
                if (sc > best) { best = sc; bi = i; }   // strict > == first occurrence
            }
            int sv = c[bi]; rem[bi] = false;
            for (int i = 0; i < 12; i++) { int dd = abs(c[i] - sv); if (dd < md[i]) md[i] = dd; }
            s_sel[s] = sv;
        }
        for (int k = 0; k < 6; k++) out_idx[b*6 + k] = (float)s_sel[k];
    }
    __syncthreads();

    for (int i = tid; i < 6*256; i += 256) {
        int k = i >> 8, d = i & 255;
        out_rep[((size_t)b*6 + k)*256 + d] = x[((size_t)b*T_ + s_sel[k])*256 + d];
    }
}

// ---------------------------------------------------------------------------
extern "C" void kernel_launch(void* const* d_in, const int* in_sizes, int n_in,
                              void* d_out, int out_size)
{
    const float* vf    = (const float*)d_in[0];
    const float* qe    = (const float*)d_in[1];
    const float* pos   = (const float*)d_in[2];
    const float* mu_w1 = (const float*)d_in[3];
    const float* mu_b1 = (const float*)d_in[4];
    const float* mu_w2 = (const float*)d_in[5];
    const float* mu_b2 = (const float*)d_in[6];
    const float* ln_g  = (const float*)d_in[7];
    const float* ln_b  = (const float*)d_in[8];
    const float* sg_w1 = (const float*)d_in[9];
    const float* sg_b1 = (const float*)d_in[10];
    const float* sg_w2 = (const float*)d_in[11];
    const float* sg_b2 = (const float*)d_in[12];
    const float* sel_w1= (const float*)d_in[13];
    const float* sel_b1= (const float*)d_in[14];
    const float* sel_w2= (const float*)d_in[15];
    const float* sel_b2= (const float*)d_in[16];

    float* out      = (float*)d_out;
    float* out_rep  = out;               // [128,6,256]
    float* out_idx  = out + 196608;      // [128,6]
    float* out_dist = out + 197376;      // [128,1000]
    float* out_mu   = out + 325376;      // [128,256]
    float* out_sig  = out + 358144;      // [128,256]
    float* out_x    = out + 390912;      // [128,1000,256]

    k_params<<<B_, 256>>>(qe, mu_w1, mu_b1, mu_w2, mu_b2, ln_g, ln_b,
                          sg_w1, sg_b1, sg_w2, sg_b2, sel_w1, sel_b1,
                          out_mu, out_sig);
    k_xdist<<<ROWS_, 256>>>(vf, pos, out_mu, out_sig, out_x, out_dist);
    k_rel<<<ROWS_/BR, 256>>>(out_x, sel_w1, sel_w2, sel_b2);
    k_select<<<B_, 256>>>(out_dist, out_x, out_rep, out_idx);
}